// round 4
// baseline (speedup 1.0000x reference)
#include <cuda_runtime.h>

#define FFTC 256
#define NL 11
#define TT 2048
#define NCTA 16
#define SPS 24                       // stages per step: 11*2 + logits + sampler
#define NFLAGS (1 + TT*SPS)
#define MEMCOLS 2047                 // sum of dilations 1+2+...+1024

// Persistent state (zeroed/recomputed every kernel_launch for determinism)
__device__ float g_mem[MEMCOLS*FFTC];        // ring buffers, layer j at offset (2^j - 1)
__device__ float g_cond[NL*16*FFTC];         // cond projections per (layer, frame)
__device__ float g_emb[256*FFTC];            // tanh(emb_raw)
__device__ __align__(16) float g_bcast[4][FFTC]; // broadcast ring (4-deep)
__device__ unsigned g_flags[NFLAGS];         // monotone per-stage counters

__device__ __forceinline__ void wait_flag(int s, unsigned expect){
  const unsigned* p = g_flags + s;
  unsigned v;
  do {
    asm volatile("ld.acquire.gpu.global.u32 %0, [%1];" : "=r"(v) : "l"(p) : "memory");
  } while (v < expect);
}
__device__ __forceinline__ void signal_flag(int s){
  __syncthreads();
  __threadfence();
  if (threadIdx.x == 0)
    asm volatile("red.release.gpu.global.add.u32 [%0], %1;" :: "l"(g_flags + s), "r"(1u) : "memory");
}

struct F16v { float4 a,b,c,d; };
__device__ __forceinline__ F16v ld16(const float* p){
  const float4* q = (const float4*)p;
  F16v r; r.a=q[0]; r.b=q[1]; r.c=q[2]; r.d=q[3]; return r;
}
__device__ __forceinline__ float dot4(float4 w, float4 v, float p){
  p = fmaf(w.x,v.x,p); p = fmaf(w.y,v.y,p); p = fmaf(w.z,v.z,p); p = fmaf(w.w,v.w,p); return p;
}
__device__ __forceinline__ float dot16(const F16v& w, const F16v& v, float p){
  p = dot4(w.a,v.a,p); p = dot4(w.b,v.b,p); p = dot4(w.c,v.c,p); p = dot4(w.d,v.d,p); return p;
}
__device__ __forceinline__ float red16(float p){
  #pragma unroll
  for (int k=8;k>0;k>>=1) p += __shfl_xor_sync(0xffffffffu, p, k);
  return p;
}

// ---------------- init: zero mutable state ----------------
__global__ void init_state(){
  int i = blockIdx.x*blockDim.x + threadIdx.x;
  int stride = gridDim.x*blockDim.x;
  for (int k=i; k<MEMCOLS*FFTC; k+=stride) g_mem[k] = 0.0f;
  for (int k=i; k<NFLAGS; k+=stride) g_flags[k] = 0u;
}

// ---------------- precompute: emb = tanh(emb_raw); cond[j][f] = condW[j] @ y[:,f] ----------------
__global__ void precompute(const float* __restrict__ y,
                           const float* __restrict__ emb_raw,
                           const float* __restrict__ condW){
  int b = blockIdx.x, tid = threadIdx.x;
  if (b < 256) {
    g_emb[b*256 + tid] = tanhf(emb_raw[b*256 + tid]);
  } else {
    int b2 = b - 256;
    int j = b2 >> 4, f = b2 & 15;
    int row = j*256 + tid;
    float acc = 0.0f;
    #pragma unroll
    for (int c=0; c<80; c++) acc = fmaf(condW[row*80 + c], y[c*16 + f], acc);
    g_cond[(j*16 + f)*256 + tid] = acc;
  }
}

// ---------------- main persistent kernel: 16 CTAs x 256 threads ----------------
// thread t: row_l = t>>4 (16 rows/CTA), seg = t&15 (16 cols of 16 elems each)
__global__ void __launch_bounds__(256,1) fftnet_main(
  const float* __restrict__ WVp, const float* __restrict__ WVc,
  const float* __restrict__ Wow, const float* __restrict__ Wob,
  const float* __restrict__ endw, const float* __restrict__ endb,
  const float* __restrict__ samples, float* __restrict__ out)
{
  const int tid = threadIdx.x;
  const int blk = blockIdx.x;
  const int row_l = tid >> 4;
  const int seg = tid & 15;
  const int r = blk*16 + row_l;         // global output row owned by this thread group
  const int c0 = seg*16;                // column chunk base
  __shared__ float s_red[8];
  __shared__ unsigned s_bal[8];
  __shared__ int s_sel;

  // initial broadcast: x0 = emb[127]
  if (blk == 0) {
    g_bcast[0][tid] = g_emb[127*256 + tid];
    signal_flag(0);
  }

  float xr = 0.0f;  // x_in[r], held by seg==0 threads

  for (int t=0; t<TT; ++t) {
    const int f = t >> 7;
    const int Sbase = 1 + t*SPS;

    #pragma unroll 1
    for (int j=0; j<NL; ++j) {
      const int col = ((1<<j) - 1) + (t & ((1<<j) - 1));  // ring column for layer j
      int S = Sbase + 2*j;
      { // ---- stage A: h = relu(cond + Wp@mem_col + Wc@x) ----
        // prefetch + pre-compute everything independent of x (hidden under the spin)
        F16v wp = ld16(WVp + (j*FFTC + r)*FFTC + c0);
        F16v mc = ld16(g_mem + col*FFTC + c0);
        F16v wc = ld16(WVc + (j*FFTC + r)*FFTC + c0);
        float part = (seg==0) ? g_cond[(j*16 + f)*FFTC + r] : 0.0f;
        part = dot16(wp, mc, part);
        wait_flag(S-1, (j==0) ? 1u : 16u);
        const float* xb = g_bcast[(S-1)&3];
        F16v xv = ld16(xb + c0);
        if (seg==0) xr = xb[r];
        part = dot16(wc, xv, part);
        part = red16(part);
        if (seg==0) g_bcast[S&3][r] = fmaxf(part, 0.0f);
        signal_flag(S);
      }
      S++;
      { // ---- stage B: x' = relu(Wo@h + b + x); deferred ring write of x ----
        F16v wo = ld16(Wow + (j*FFTC + r)*FFTC + c0);
        float part = (seg==0) ? Wob[j*FFTC + r] : 0.0f;
        wait_flag(S-1, 16u);
        if (seg==0) g_mem[col*FFTC + r] = xr;  // safe: all stage-A reads done chip-wide
        const float* hb = g_bcast[(S-1)&3];
        F16v hv = ld16(hb + c0);
        part = dot16(wo, hv, part);
        part = red16(part);
        if (seg==0) g_bcast[S&3][r] = fmaxf(part + xr, 0.0f);
        signal_flag(S);
      }
    }

    int S = Sbase + 22;
    { // ---- logits = end_w @ x + end_b ----
      F16v ew = ld16(endw + r*FFTC + c0);
      float part = (seg==0) ? endb[r] : 0.0f;
      wait_flag(S-1, 16u);
      const float* xb = g_bcast[(S-1)&3];
      F16v xv = ld16(xb + c0);
      part = dot16(ew, xv, part);
      part = red16(part);
      if (seg==0) g_bcast[S&3][r] = part;  // C_SCALE == 1.0
      signal_flag(S);
    }
    S++;

    if (blk == 0) { // ---- sampler: softmax -> cumsum -> first(cum > u) -> x0 = emb[idx] ----
      wait_flag(S-1, 16u);
      const float* lb = g_bcast[(S-1)&3];
      float l = lb[tid];
      const int lane = tid & 31, w = tid >> 5;
      // block max
      float m = l;
      #pragma unroll
      for (int k=16;k>0;k>>=1) m = fmaxf(m, __shfl_xor_sync(0xffffffffu, m, k));
      if (lane==0) s_red[w] = m;
      __syncthreads();
      float M = s_red[0];
      #pragma unroll
      for (int i=1;i<8;i++) M = fmaxf(M, s_red[i]);
      float e = expf(l - M);
      // block sum
      float sg = e;
      #pragma unroll
      for (int k=16;k>0;k>>=1) sg += __shfl_xor_sync(0xffffffffu, sg, k);
      __syncthreads();
      if (lane==0) s_red[w] = sg;
      __syncthreads();
      float tot = 0.0f;
      #pragma unroll
      for (int i=0;i<8;i++) tot += s_red[i];
      float p = e / tot;
      // inclusive scan of p
      float csum = p;
      #pragma unroll
      for (int k=1;k<32;k<<=1) { float o = __shfl_up_sync(0xffffffffu, csum, k); if (lane>=k) csum += o; }
      __syncthreads();
      if (lane==31) s_red[w] = csum;
      __syncthreads();
      float carry = 0.0f;
      for (int i=0;i<w;i++) carry += s_red[i];
      csum += carry;
      float u = samples[t];
      unsigned bal = __ballot_sync(0xffffffffu, csum > u);
      if (lane==0) s_bal[w] = bal;
      __syncthreads();
      if (tid==0) {
        int sel = 0;   // argmax of bool: first true; 0 if none
        #pragma unroll
        for (int i=7;i>=0;i--) { unsigned b = s_bal[i]; if (b) sel = i*32 + __ffs((int)b) - 1; }
        s_sel = sel;
        out[t] = (float)sel;   // __output__ is float32: store the index as a float value
      }
      __syncthreads();
      g_bcast[S&3][tid] = g_emb[s_sel*FFTC + tid];
      signal_flag(S);
    }
  }
}

extern "C" void kernel_launch(void* const* d_in, const int* in_sizes, int n_in,
                              void* d_out, int out_size) {
  // ---- Robust input binding: identify tensors by element count, not position.
  // Unique sizes: y=1280, samples=2048, condW=225280, Wob=2816, endb=256.
  // Ambiguous: {emb_raw, end_w}=65536 (emb_raw first in every plausible ordering);
  // {WV_past, WV_present, W_o_w}=720896, disambiguated by how many of the trio
  // precede W_o_b (2816): 3 or 2 -> (WVp, WVc, Wow); 0 -> (Wow, WVp, WVc).
  int i1280=-1, i2048=-1, i225280=-1, i2816=-1, i256=-1;
  int i65536[2] = {-1,-1}; int n65536 = 0;
  int i720[3] = {-1,-1,-1}; int n720 = 0;
  for (int i=0;i<n_in;i++){
    switch (in_sizes[i]){
      case 1280:   i1280 = i; break;
      case 2048:   i2048 = i; break;
      case 225280: i225280 = i; break;
      case 2816:   i2816 = i; break;
      case 256:    i256 = i; break;
      case 65536:  if (n65536 < 2) i65536[n65536++] = i; break;
      case 720896: if (n720 < 3) i720[n720++] = i; break;
      default: break;
    }
  }
  // Fallback to insertion-order if detection incomplete
  if (i1280<0 || i2048<0 || i225280<0 || i2816<0 || i256<0 || n65536!=2 || n720!=3){
    i1280=0; i2048=1; i65536[0]=2; i225280=3; i720[0]=4; i720[1]=5; i720[2]=6;
    i2816=7; i65536[1]=8; i256=9;
  }
  const float* y        = (const float*)d_in[i1280];     // [80,16]
  const float* samples  = (const float*)d_in[i2048];     // [2048]
  const float* condW    = (const float*)d_in[i225280];   // [2816,80]
  const float* Wob      = (const float*)d_in[i2816];     // [11,256]
  const float* endb     = (const float*)d_in[i256];      // [256]
  const float* emb_raw  = (const float*)d_in[i65536[0]]; // [256,256]
  const float* endw     = (const float*)d_in[i65536[1]]; // [256,256]
  int before = 0;
  for (int k=0;k<3;k++) if (i720[k] < i2816) before++;
  const float *WVp, *WVc, *Wow;
  if (before == 0) { Wow = (const float*)d_in[i720[0]];
                     WVp = (const float*)d_in[i720[1]];
                     WVc = (const float*)d_in[i720[2]]; }
  else             { WVp = (const float*)d_in[i720[0]];
                     WVc = (const float*)d_in[i720[1]];
                     Wow = (const float*)d_in[i720[2]]; }
  float* out = (float*)d_out;                            // [2048] sampled class ids (as float32)

  init_state<<<256,256>>>();
  precompute<<<256 + NL*16, 256>>>(y, emb_raw, condW);
  fftnet_main<<<NCTA,256>>>(WVp, WVc, Wow, Wob, endw, endb, samples, out);
}

// round 5
// speedup vs baseline: 1.0868x; 1.0868x over previous
#include <cuda_runtime.h>

#define FFTC 256
#define NL 11
#define TT 2048
#define NCTA 16
#define SPS 24                       // stages per step: 11*2 + logits + sampler
#define NFLAGS (1 + TT*SPS)
#define FSTRIDE 32                   // one 128B L2 line per flag (no false sharing)
#define MEMCOLS 2047                 // sum of dilations 1+2+...+1024

// Persistent state (zeroed/recomputed every kernel_launch for determinism)
__device__ float g_mem[MEMCOLS*FFTC];        // ring buffers, layer j at offset (2^j - 1)
__device__ float g_cond[NL*16*FFTC];         // cond projections per (layer, frame)
__device__ float g_emb[256*FFTC];            // tanh(emb_raw)
__device__ __align__(16) float g_bcast[4][FFTC]; // broadcast ring (4-deep)
__device__ unsigned g_flags[(size_t)NFLAGS*FSTRIDE]; // monotone per-stage counters, padded

__device__ __forceinline__ void poll_flag(int s, unsigned expect){
  const unsigned* p = g_flags + (size_t)s*FSTRIDE;
  unsigned v;
  do {
    asm volatile("ld.acquire.gpu.global.u32 %0, [%1];" : "=r"(v) : "l"(p) : "memory");
  } while (v < expect);
}
// per-warp wait: only lane 0 polls, rest of warp waits at syncwarp
__device__ __forceinline__ void wait_flag(int s, unsigned expect){
  if ((threadIdx.x & 31) == 0) poll_flag(s, expect);
  __syncwarp();
}
// CTA-wide signal: bar then one release-atomic (CG grid-sync pattern; no fence needed)
__device__ __forceinline__ void signal_flag(int s){
  __syncthreads();
  if (threadIdx.x == 0)
    asm volatile("red.release.gpu.global.add.u32 [%0], %1;"
                 :: "l"(g_flags + (size_t)s*FSTRIDE), "r"(1u) : "memory");
}

struct F16v { float4 a,b,c,d; };
__device__ __forceinline__ F16v ld16(const float* p){
  const float4* q = (const float4*)p;
  F16v r; r.a=q[0]; r.b=q[1]; r.c=q[2]; r.d=q[3]; return r;
}
__device__ __forceinline__ float dot4(float4 w, float4 v, float p){
  p = fmaf(w.x,v.x,p); p = fmaf(w.y,v.y,p); p = fmaf(w.z,v.z,p); p = fmaf(w.w,v.w,p); return p;
}
__device__ __forceinline__ float dot16(const F16v& w, const F16v& v, float p){
  p = dot4(w.a,v.a,p); p = dot4(w.b,v.b,p); p = dot4(w.c,v.c,p); p = dot4(w.d,v.d,p); return p;
}
__device__ __forceinline__ float red16(float p){
  #pragma unroll
  for (int k=8;k>0;k>>=1) p += __shfl_xor_sync(0xffffffffu, p, k);
  return p;
}

// ---------------- init: zero mutable state ----------------
__global__ void init_state(){
  size_t i = (size_t)blockIdx.x*blockDim.x + threadIdx.x;
  size_t stride = (size_t)gridDim.x*blockDim.x;
  for (size_t k=i; k<(size_t)MEMCOLS*FFTC; k+=stride) g_mem[k] = 0.0f;
  for (size_t k=i; k<(size_t)NFLAGS*FSTRIDE; k+=stride) g_flags[k] = 0u;
}

// ---------------- precompute: emb = tanh(emb_raw); cond[j][f] = condW[j] @ y[:,f] ----------------
__global__ void precompute(const float* __restrict__ y,
                           const float* __restrict__ emb_raw,
                           const float* __restrict__ condW){
  int b = blockIdx.x, tid = threadIdx.x;
  if (b < 256) {
    g_emb[b*256 + tid] = tanhf(emb_raw[b*256 + tid]);
  } else {
    int b2 = b - 256;
    int j = b2 >> 4, f = b2 & 15;
    int row = j*256 + tid;
    float acc = 0.0f;
    #pragma unroll
    for (int c=0; c<80; c++) acc = fmaf(condW[row*80 + c], y[c*16 + f], acc);
    g_cond[(j*16 + f)*256 + tid] = acc;
  }
}

// ---------------- main persistent kernel: 16 CTAs x 256 threads ----------------
// thread t: row_l = t>>4 (16 rows/CTA), seg = t&15 (16 cols of 16 elems each)
__global__ void __launch_bounds__(256,1) fftnet_main(
  const float* __restrict__ WVp, const float* __restrict__ WVc,
  const float* __restrict__ Wow, const float* __restrict__ Wob,
  const float* __restrict__ endw, const float* __restrict__ endb,
  const float* __restrict__ samples, float* __restrict__ out)
{
  const int tid = threadIdx.x;
  const int blk = blockIdx.x;
  const int row_l = tid >> 4;
  const int seg = tid & 15;
  const int r = blk*16 + row_l;         // global output row owned by this thread group
  const int c0 = seg*16;                // column chunk base

  // initial broadcast: x0 = emb[127]
  if (blk == 0) {
    g_bcast[0][tid] = g_emb[127*256 + tid];
    signal_flag(0);
  }

  float xr = 0.0f;  // x_in[r], held by seg==0 threads

  for (int t=0; t<TT; ++t) {
    const int f = t >> 7;
    const int Sbase = 1 + t*SPS;

    #pragma unroll 1
    for (int j=0; j<NL; ++j) {
      const int col = ((1<<j) - 1) + (t & ((1<<j) - 1));  // ring column for layer j
      int S = Sbase + 2*j;
      { // ---- stage A: h = relu(cond + Wp@mem_col + Wc@x) ----
        // prefetch + pre-compute everything independent of x (hidden under the spin)
        F16v wp = ld16(WVp + (j*FFTC + r)*FFTC + c0);
        F16v mc = ld16(g_mem + col*FFTC + c0);
        F16v wc = ld16(WVc + (j*FFTC + r)*FFTC + c0);
        float part = (seg==0) ? g_cond[(j*16 + f)*FFTC + r] : 0.0f;
        part = dot16(wp, mc, part);
        wait_flag(S-1, (j==0) ? 1u : (unsigned)NCTA);
        const float* xb = g_bcast[(S-1)&3];
        F16v xv = ld16(xb + c0);
        if (seg==0) xr = xb[r];
        part = dot16(wc, xv, part);
        part = red16(part);
        if (seg==0) g_bcast[S&3][r] = fmaxf(part, 0.0f);
        signal_flag(S);
      }
      S++;
      { // ---- stage B: x' = relu(Wo@h + b + x); deferred ring write of x ----
        F16v wo = ld16(Wow + (j*FFTC + r)*FFTC + c0);
        float part = (seg==0) ? Wob[j*FFTC + r] : 0.0f;
        wait_flag(S-1, NCTA);
        if (seg==0) g_mem[col*FFTC + r] = xr;  // safe: all stage-A reads done chip-wide
        const float* hb = g_bcast[(S-1)&3];
        F16v hv = ld16(hb + c0);
        part = dot16(wo, hv, part);
        part = red16(part);
        if (seg==0) g_bcast[S&3][r] = fmaxf(part + xr, 0.0f);
        signal_flag(S);
      }
    }

    int S = Sbase + 22;
    { // ---- logits = end_w @ x + end_b ----
      F16v ew = ld16(endw + r*FFTC + c0);
      float part = (seg==0) ? endb[r] : 0.0f;
      wait_flag(S-1, NCTA);
      const float* xb = g_bcast[(S-1)&3];
      F16v xv = ld16(xb + c0);
      part = dot16(ew, xv, part);
      part = red16(part);
      if (seg==0) g_bcast[S&3][r] = part;  // C_SCALE == 1.0
      signal_flag(S);
    }
    S++;

    // ---- sampler (warp 0 of block 0 only): softmax -> cumsum -> first(cum > u) ----
    if (blk == 0 && (tid >> 5) == 0) {
      const int lane = tid & 31;
      float u = samples[t];                    // prefetch before the spin
      if (lane == 0) poll_flag(S-1, NCTA);
      __syncwarp();
      const float* lb = g_bcast[(S-1)&3];
      float4 va = *(const float4*)(lb + lane*8);
      float4 vb = *(const float4*)(lb + lane*8 + 4);
      float v[8] = {va.x,va.y,va.z,va.w,vb.x,vb.y,vb.z,vb.w};
      // warp max
      float m = v[0];
      #pragma unroll
      for (int k=1;k<8;k++) m = fmaxf(m, v[k]);
      #pragma unroll
      for (int k=16;k>0;k>>=1) m = fmaxf(m, __shfl_xor_sync(0xffffffffu, m, k));
      // exp + warp total
      float e[8]; float sl = 0.0f;
      #pragma unroll
      for (int k=0;k<8;k++){ e[k] = expf(v[k] - m); sl += e[k]; }
      float tot = sl;
      #pragma unroll
      for (int k=16;k>0;k>>=1) tot += __shfl_xor_sync(0xffffffffu, tot, k);
      // per-lane sequential cumsum of p = e/tot
      float cs[8]; float c = 0.0f;
      #pragma unroll
      for (int k=0;k<8;k++){ c += e[k] / tot; cs[k] = c; }
      // exclusive prefix of per-lane totals (Kogge-Stone inclusive, shifted)
      float inc = c;
      #pragma unroll
      for (int k=1;k<32;k<<=1){ float o = __shfl_up_sync(0xffffffffu, inc, k); if (lane>=k) inc += o; }
      float off = __shfl_up_sync(0xffffffffu, inc, 1);
      if (lane == 0) off = 0.0f;
      // first index with cumsum > u
      int cand = 1<<30;
      #pragma unroll
      for (int k=0;k<8;k++) if (cand == (1<<30) && (off + cs[k]) > u) cand = lane*8 + k;
      #pragma unroll
      for (int k=16;k>0;k>>=1) cand = min(cand, __shfl_xor_sync(0xffffffffu, cand, k));
      int sel = (cand >= 256) ? 0 : cand;
      if (lane == 0) out[t] = (float)sel;
      // broadcast emb[sel] for next step
      float4 e0 = *(const float4*)(g_emb + sel*256 + lane*8);
      float4 e1 = *(const float4*)(g_emb + sel*256 + lane*8 + 4);
      *(float4*)(g_bcast[S&3] + lane*8)     = e0;
      *(float4*)(g_bcast[S&3] + lane*8 + 4) = e1;
      __syncwarp();
      if (lane == 0)
        asm volatile("red.release.gpu.global.add.u32 [%0], %1;"
                     :: "l"(g_flags + (size_t)S*FSTRIDE), "r"(1u) : "memory");
    }
  }
}

extern "C" void kernel_launch(void* const* d_in, const int* in_sizes, int n_in,
                              void* d_out, int out_size) {
  // ---- Robust input binding: identify tensors by element count, not position.
  int i1280=-1, i2048=-1, i225280=-1, i2816=-1, i256=-1;
  int i65536[2] = {-1,-1}; int n65536 = 0;
  int i720[3] = {-1,-1,-1}; int n720 = 0;
  for (int i=0;i<n_in;i++){
    switch (in_sizes[i]){
      case 1280:   i1280 = i; break;
      case 2048:   i2048 = i; break;
      case 225280: i225280 = i; break;
      case 2816:   i2816 = i; break;
      case 256:    i256 = i; break;
      case 65536:  if (n65536 < 2) i65536[n65536++] = i; break;
      case 720896: if (n720 < 3) i720[n720++] = i; break;
      default: break;
    }
  }
  if (i1280<0 || i2048<0 || i225280<0 || i2816<0 || i256<0 || n65536!=2 || n720!=3){
    i1280=0; i2048=1; i65536[0]=2; i225280=3; i720[0]=4; i720[1]=5; i720[2]=6;
    i2816=7; i65536[1]=8; i256=9;
  }
  const float* y        = (const float*)d_in[i1280];     // [80,16]
  const float* samples  = (const float*)d_in[i2048];     // [2048]
  const float* condW    = (const float*)d_in[i225280];   // [2816,80]
  const float* Wob      = (const float*)d_in[i2816];     // [11,256]
  const float* endb     = (const float*)d_in[i256];      // [256]
  const float* emb_raw  = (const float*)d_in[i65536[0]]; // [256,256]
  const float* endw     = (const float*)d_in[i65536[1]]; // [256,256]
  int before = 0;
  for (int k=0;k<3;k++) if (i720[k] < i2816) before++;
  const float *WVp, *WVc, *Wow;
  if (before == 0) { Wow = (const float*)d_in[i720[0]];
                     WVp = (const float*)d_in[i720[1]];
                     WVc = (const float*)d_in[i720[2]]; }
  else             { WVp = (const float*)d_in[i720[0]];
                     WVc = (const float*)d_in[i720[1]];
                     Wow = (const float*)d_in[i720[2]]; }
  float* out = (float*)d_out;                            // [2048] sampled ids (as float32)

  init_state<<<256,256>>>();
  precompute<<<256 + NL*16, 256>>>(y, emb_raw, condW);
  fftnet_main<<<NCTA,256>>>(WVp, WVc, Wow, Wob, endw, endb, samples, out);
}